// round 3
// baseline (speedup 1.0000x reference)
#include <cuda_runtime.h>
#include <math.h>

// Problem constants
#define BATCH 8
#define SEQ   4096
#define DDIM  512
#define NE    16
#define MDIM  1024
#define NTOK  (BATCH * SEQ)      // 32768 tokens
#define NSLOT (NTOK * 2)         // 65536 token-expert slots (top-2)

// ---------------- static device scratch (no allocations allowed) ----------------
__device__ int   g_counts[NE];
__device__ int   g_offsets[NE + 1];
__device__ int   g_bkt_tok[NE * NTOK];      // 2 MB
__device__ float g_bkt_w[NE * NTOK];        // 2 MB
__device__ int   g_tok[NSLOT];
__device__ float g_wgt[NSLOT];
__device__ float g_h[(size_t)NSLOT * MDIM]; // 256 MB intermediate h

// ---------------- helpers ----------------
__global__ void zero_out_kernel(float* __restrict__ out) {
    size_t i = ((size_t)blockIdx.x * blockDim.x + threadIdx.x) * 4;
    float4 z = make_float4(0.f, 0.f, 0.f, 0.f);
    *(float4*)(out + i) = z;
}

__global__ void zero_counts_kernel() {
    if (threadIdx.x < NE) g_counts[threadIdx.x] = 0;
}

__global__ void offsets_kernel() {
    if (threadIdx.x == 0) {
        int s = 0;
        for (int e = 0; e < NE; e++) { g_offsets[e] = s; s += g_counts[e]; }
        g_offsets[NE] = s;
    }
}

__global__ void compact_kernel() {
    int e = blockIdx.y;
    int i = blockIdx.x * 256 + threadIdx.x;
    int cnt = g_counts[e];
    if (i < cnt) {
        int slot = g_offsets[e] + i;
        g_tok[slot] = g_bkt_tok[e * NTOK + i];
        g_wgt[slot] = g_bkt_w[e * NTOK + i];
    }
}

// ---------------- routing: gate logits + top-2 + softmax + scatter ----------------
// warp per token; wg cached in smem padded to stride 17 (conflict-free)
__global__ __launch_bounds__(256) void route_kernel(
        const float* __restrict__ x, const float* __restrict__ wg) {
    __shared__ float swg[DDIM * 17];   // 512 x 16 padded -> ~35 KB
    int tid = threadIdx.x;
    for (int i = tid; i < DDIM * NE; i += 256) {
        int d = i >> 4, e = i & 15;
        swg[d * 17 + e] = wg[i];
    }
    __syncthreads();

    int warp = tid >> 5, lane = tid & 31;
    int t = blockIdx.x * 8 + warp;
    const float* xr = x + (size_t)t * DDIM;

    float acc[NE];
#pragma unroll
    for (int e = 0; e < NE; e++) acc[e] = 0.f;

    for (int d = lane; d < DDIM; d += 32) {
        float xv = xr[d];
        const float* w = &swg[d * 17];
#pragma unroll
        for (int e = 0; e < NE; e++) acc[e] += xv * w[e];
    }
#pragma unroll
    for (int e = 0; e < NE; e++) {
#pragma unroll
        for (int o = 16; o > 0; o >>= 1)
            acc[e] += __shfl_xor_sync(0xffffffffu, acc[e], o);
    }

    if (lane == 0) {
        // top-2 with lowest-index tie break (matches jax top_k)
        int e0 = 0; float v0 = acc[0];
#pragma unroll
        for (int e = 1; e < NE; e++) if (acc[e] > v0) { v0 = acc[e]; e0 = e; }
        int e1 = -1; float v1 = -INFINITY;
#pragma unroll
        for (int e = 0; e < NE; e++) if (e != e0 && acc[e] > v1) { v1 = acc[e]; e1 = e; }
        float wa = 1.f / (1.f + expf(v1 - v0));   // softmax over [v0, v1]
        float wb = 1.f - wa;
        int p0 = atomicAdd(&g_counts[e0], 1);
        g_bkt_tok[e0 * NTOK + p0] = t; g_bkt_w[e0 * NTOK + p0] = wa;
        int p1 = atomicAdd(&g_counts[e1], 1);
        g_bkt_tok[e1 * NTOK + p1] = t; g_bkt_w[e1 * NTOK + p1] = wb;
    }
}

// ---------------- GEMM1: h = silu(X @ w0) * (X @ w1), gathered rows ----------------
// tile 128(M) x 64(N), K=512 in chunks of 16, 256 threads, 8x4 microtile x 2 matrices
__global__ __launch_bounds__(256, 2) void gemm1_kernel(
        const float* __restrict__ x, const float* __restrict__ w0,
        const float* __restrict__ w1) {
    const int e    = blockIdx.z;
    const int base = g_offsets[e];
    const int cnt  = g_offsets[e + 1] - base;
    const int row0 = blockIdx.y * 128;
    if (row0 >= cnt) return;
    const int n0 = blockIdx.x * 64;

    __shared__ float As[16][128];
    __shared__ float B0s[16][64];
    __shared__ float B1s[16][64];
    __shared__ int   stok[128];

    const int tid = threadIdx.x;
    if (tid < 128) {
        int r = row0 + tid;
        stok[tid] = (r < cnt) ? g_tok[base + r] : -1;
    }
    __syncthreads();

    const int arow = tid >> 1;
    const int aq   = (tid & 1) << 3;            // 0 or 8
    const int atok = stok[arow];
    const float* aptr = (atok >= 0) ? (x + (size_t)atok * DDIM + aq) : nullptr;

    const int bk = tid >> 4;                    // 0..15
    const int bn = (tid & 15) << 2;             // 0..60
    const float* b0p = w0 + ((size_t)e * DDIM + bk) * MDIM + n0 + bn;
    const float* b1p = w1 + ((size_t)e * DDIM + bk) * MDIM + n0 + bn;

    const int ty = tid >> 4;
    const int tx = tid & 15;

    float c0[8][4], c1[8][4];
#pragma unroll
    for (int i = 0; i < 8; i++)
#pragma unroll
        for (int j = 0; j < 4; j++) { c0[i][j] = 0.f; c1[i][j] = 0.f; }

    for (int kk = 0; kk < DDIM; kk += 16) {
        float4 va0 = make_float4(0.f, 0.f, 0.f, 0.f), va1 = va0;
        if (aptr) {
            va0 = *(const float4*)(aptr + kk);
            va1 = *(const float4*)(aptr + kk + 4);
        }
        As[aq + 0][arow] = va0.x; As[aq + 1][arow] = va0.y;
        As[aq + 2][arow] = va0.z; As[aq + 3][arow] = va0.w;
        As[aq + 4][arow] = va1.x; As[aq + 5][arow] = va1.y;
        As[aq + 6][arow] = va1.z; As[aq + 7][arow] = va1.w;
        *(float4*)&B0s[bk][bn] = *(const float4*)(b0p + (size_t)kk * MDIM);
        *(float4*)&B1s[bk][bn] = *(const float4*)(b1p + (size_t)kk * MDIM);
        __syncthreads();

#pragma unroll
        for (int k = 0; k < 16; k++) {
            float a[8], b0[4], b1[4];
            *(float4*)&a[0] = *(const float4*)&As[k][ty * 8];
            *(float4*)&a[4] = *(const float4*)&As[k][ty * 8 + 4];
            *(float4*)&b0[0] = *(const float4*)&B0s[k][tx * 4];
            *(float4*)&b1[0] = *(const float4*)&B1s[k][tx * 4];
#pragma unroll
            for (int i = 0; i < 8; i++)
#pragma unroll
                for (int j = 0; j < 4; j++) {
                    c0[i][j] += a[i] * b0[j];
                    c1[i][j] += a[i] * b1[j];
                }
        }
        __syncthreads();
    }

    // epilogue: h = silu(c0) * c1
#pragma unroll
    for (int i = 0; i < 8; i++) {
        int r = ty * 8 + i;
        if (row0 + r < cnt) {
            float4 v;
            float g;
            g = c0[i][0]; v.x = (g / (1.f + __expf(-g))) * c1[i][0];
            g = c0[i][1]; v.y = (g / (1.f + __expf(-g))) * c1[i][1];
            g = c0[i][2]; v.z = (g / (1.f + __expf(-g))) * c1[i][2];
            g = c0[i][3]; v.w = (g / (1.f + __expf(-g))) * c1[i][3];
            *(float4*)(g_h + (size_t)(base + row0 + r) * MDIM + n0 + tx * 4) = v;
        }
    }
}

// ---------------- GEMM2: out += wgt * (H @ wo), scatter via atomicAdd ----------------
__global__ __launch_bounds__(256, 2) void gemm2_kernel(
        const float* __restrict__ wo, float* __restrict__ out) {
    const int e    = blockIdx.z;
    const int base = g_offsets[e];
    const int cnt  = g_offsets[e + 1] - base;
    const int row0 = blockIdx.y * 128;
    if (row0 >= cnt) return;
    const int n0 = blockIdx.x * 64;

    __shared__ float As[16][128];
    __shared__ float Bs[16][64];
    __shared__ int   stok[128];
    __shared__ float sw[128];

    const int tid = threadIdx.x;
    if (tid < 128) {
        int r = row0 + tid;
        stok[tid] = (r < cnt) ? g_tok[base + r] : -1;
        sw[tid]   = (r < cnt) ? g_wgt[base + r] : 0.f;
    }
    __syncthreads();

    const int arow = tid >> 1;
    const int aq   = (tid & 1) << 3;
    const bool avalid = (row0 + arow) < cnt;
    const float* aptr = g_h + (size_t)(base + row0 + arow) * MDIM + aq;

    const int bk = tid >> 4;
    const int bn = (tid & 15) << 2;
    const float* bp = wo + ((size_t)e * MDIM + bk) * DDIM + n0 + bn;

    const int ty = tid >> 4;
    const int tx = tid & 15;

    float c[8][4];
#pragma unroll
    for (int i = 0; i < 8; i++)
#pragma unroll
        for (int j = 0; j < 4; j++) c[i][j] = 0.f;

    for (int kk = 0; kk < MDIM; kk += 16) {
        float4 va0 = make_float4(0.f, 0.f, 0.f, 0.f), va1 = va0;
        if (avalid) {
            va0 = *(const float4*)(aptr + kk);
            va1 = *(const float4*)(aptr + kk + 4);
        }
        As[aq + 0][arow] = va0.x; As[aq + 1][arow] = va0.y;
        As[aq + 2][arow] = va0.z; As[aq + 3][arow] = va0.w;
        As[aq + 4][arow] = va1.x; As[aq + 5][arow] = va1.y;
        As[aq + 6][arow] = va1.z; As[aq + 7][arow] = va1.w;
        *(float4*)&Bs[bk][bn] = *(const float4*)(bp + (size_t)kk * DDIM);
        __syncthreads();

#pragma unroll
        for (int k = 0; k < 16; k++) {
            float a[8], b[4];
            *(float4*)&a[0] = *(const float4*)&As[k][ty * 8];
            *(float4*)&a[4] = *(const float4*)&As[k][ty * 8 + 4];
            *(float4*)&b[0] = *(const float4*)&Bs[k][tx * 4];
#pragma unroll
            for (int i = 0; i < 8; i++)
#pragma unroll
                for (int j = 0; j < 4; j++) c[i][j] += a[i] * b[j];
        }
        __syncthreads();
    }

#pragma unroll
    for (int i = 0; i < 8; i++) {
        int r = ty * 8 + i;
        if (row0 + r < cnt) {
            int   t = stok[r];
            float w = sw[r];
            float* op = out + (size_t)t * DDIM + n0 + tx * 4;
            atomicAdd(op + 0, w * c[i][0]);
            atomicAdd(op + 1, w * c[i][1]);
            atomicAdd(op + 2, w * c[i][2]);
            atomicAdd(op + 3, w * c[i][3]);
        }
    }
}

// ---------------- launch ----------------
extern "C" void kernel_launch(void* const* d_in, const int* in_sizes, int n_in,
                              void* d_out, int out_size) {
    const float* x  = (const float*)d_in[0];
    const float* wg = (const float*)d_in[1];
    const float* w0 = (const float*)d_in[2];
    const float* w1 = (const float*)d_in[3];
    const float* wo = (const float*)d_in[4];
    float* out = (float*)d_out;

    (void)in_sizes; (void)n_in; (void)out_size;

    // out is 16,777,216 floats -> 4 per thread, 256 threads/block
    zero_out_kernel<<<NTOK * DDIM / (256 * 4), 256>>>(out);
    zero_counts_kernel<<<1, 32>>>();
    route_kernel<<<NTOK / 8, 256>>>(x, wg);
    offsets_kernel<<<1, 32>>>();
    compact_kernel<<<dim3(NTOK / 256, NE), 256>>>();
    // gemm1: N-tiles = 1024/64 = 16, worst-case M-tiles = 32768/128 = 256, E = 16
    gemm1_kernel<<<dim3(16, 256, NE), 256>>>(x, w0, w1);
    // gemm2: N-tiles = 512/64 = 8
    gemm2_kernel<<<dim3(8, 256, NE), 256>>>(wo, out);
}

// round 5
// speedup vs baseline: 1.0553x; 1.0553x over previous
#include <cuda_runtime.h>
#include <math.h>

// Problem constants
#define BATCH 8
#define SEQ   4096
#define DDIM  512
#define NE    16
#define MDIM  1024
#define NTOK  (BATCH * SEQ)      // 32768 tokens
#define NSLOT (NTOK * 2)         // 65536 token-expert slots (top-2)

// ---------------- static device scratch (no allocations allowed) ----------------
__device__ int   g_counts[NE];
__device__ int   g_offsets[NE + 1];
__device__ int   g_bkt_tok[NE * NTOK];      // 2 MB
__device__ float g_bkt_w[NE * NTOK];        // 2 MB
__device__ int   g_tok[NSLOT];
__device__ float g_wgt[NSLOT];
__device__ float g_h[(size_t)NSLOT * MDIM]; // 256 MB intermediate h

// ---------------- helpers ----------------
__global__ void zero_out_kernel(float* __restrict__ out) {
    size_t i = ((size_t)blockIdx.x * blockDim.x + threadIdx.x) * 4;
    float4 z = make_float4(0.f, 0.f, 0.f, 0.f);
    *(float4*)(out + i) = z;
}

__global__ void zero_counts_kernel() {
    if (threadIdx.x < NE) g_counts[threadIdx.x] = 0;
}

__global__ void offsets_kernel() {
    if (threadIdx.x == 0) {
        int s = 0;
        for (int e = 0; e < NE; e++) { g_offsets[e] = s; s += g_counts[e]; }
        g_offsets[NE] = s;
    }
}

__global__ void compact_kernel() {
    int e = blockIdx.y;
    int i = blockIdx.x * 256 + threadIdx.x;
    int cnt = g_counts[e];
    if (i < cnt) {
        int slot = g_offsets[e] + i;
        g_tok[slot] = g_bkt_tok[e * NTOK + i];
        g_wgt[slot] = g_bkt_w[e * NTOK + i];
    }
}

// ---------------- routing: gate logits + top-2 + softmax + scatter ----------------
// warp per token; wg cached in smem padded to stride 17 (conflict-free)
__global__ __launch_bounds__(256) void route_kernel(
        const float* __restrict__ x, const float* __restrict__ wg) {
    __shared__ float swg[DDIM * 17];   // 512 x 16 padded -> ~35 KB
    int tid = threadIdx.x;
    for (int i = tid; i < DDIM * NE; i += 256) {
        int d = i >> 4, e = i & 15;
        swg[d * 17 + e] = wg[i];
    }
    __syncthreads();

    int warp = tid >> 5, lane = tid & 31;
    int t = blockIdx.x * 8 + warp;
    const float* xr = x + (size_t)t * DDIM;

    float acc[NE];
#pragma unroll
    for (int e = 0; e < NE; e++) acc[e] = 0.f;

    for (int d = lane; d < DDIM; d += 32) {
        float xv = xr[d];
        const float* w = &swg[d * 17];
#pragma unroll
        for (int e = 0; e < NE; e++) acc[e] += xv * w[e];
    }
#pragma unroll
    for (int e = 0; e < NE; e++) {
#pragma unroll
        for (int o = 16; o > 0; o >>= 1)
            acc[e] += __shfl_xor_sync(0xffffffffu, acc[e], o);
    }

    if (lane == 0) {
        // top-2 with lowest-index tie break (matches jax top_k)
        int e0 = 0; float v0 = acc[0];
#pragma unroll
        for (int e = 1; e < NE; e++) if (acc[e] > v0) { v0 = acc[e]; e0 = e; }
        int e1 = -1; float v1 = -INFINITY;
#pragma unroll
        for (int e = 0; e < NE; e++) if (e != e0 && acc[e] > v1) { v1 = acc[e]; e1 = e; }
        float wa = 1.f / (1.f + expf(v1 - v0));   // softmax over [v0, v1]
        float wb = 1.f - wa;
        int p0 = atomicAdd(&g_counts[e0], 1);
        g_bkt_tok[e0 * NTOK + p0] = t; g_bkt_w[e0 * NTOK + p0] = wa;
        int p1 = atomicAdd(&g_counts[e1], 1);
        g_bkt_tok[e1 * NTOK + p1] = t; g_bkt_w[e1 * NTOK + p1] = wb;
    }
}

// ---------------- GEMM1: h = silu(X @ w0) * (X @ w1), gathered rows ----------------
// tile 128(M) x 64(N), K=512 in chunks of 16, 256 threads, 8x4 microtile x 2 matrices
__global__ __launch_bounds__(256, 2) void gemm1_kernel(
        const float* __restrict__ x, const float* __restrict__ w0,
        const float* __restrict__ w1) {
    const int e    = blockIdx.z;
    const int base = g_offsets[e];
    const int cnt  = g_offsets[e + 1] - base;
    const int row0 = blockIdx.y * 128;
    if (row0 >= cnt) return;
    const int n0 = blockIdx.x * 64;

    __shared__ float As[16][128];
    __shared__ float B0s[16][64];
    __shared__ float B1s[16][64];
    __shared__ int   stok[128];

    const int tid = threadIdx.x;
    if (tid < 128) {
        int r = row0 + tid;
        stok[tid] = (r < cnt) ? g_tok[base + r] : -1;
    }
    __syncthreads();

    const int arow = tid >> 1;
    const int aq   = (tid & 1) << 3;            // 0 or 8
    const int atok = stok[arow];
    const float* aptr = (atok >= 0) ? (x + (size_t)atok * DDIM + aq) : nullptr;

    const int bk = tid >> 4;                    // 0..15
    const int bn = (tid & 15) << 2;             // 0..60
    const float* b0p = w0 + ((size_t)e * DDIM + bk) * MDIM + n0 + bn;
    const float* b1p = w1 + ((size_t)e * DDIM + bk) * MDIM + n0 + bn;

    const int ty = tid >> 4;
    const int tx = tid & 15;

    float c0[8][4], c1[8][4];
#pragma unroll
    for (int i = 0; i < 8; i++)
#pragma unroll
        for (int j = 0; j < 4; j++) { c0[i][j] = 0.f; c1[i][j] = 0.f; }

    for (int kk = 0; kk < DDIM; kk += 16) {
        float4 va0 = make_float4(0.f, 0.f, 0.f, 0.f), va1 = va0;
        if (aptr) {
            va0 = *(const float4*)(aptr + kk);
            va1 = *(const float4*)(aptr + kk + 4);
        }
        As[aq + 0][arow] = va0.x; As[aq + 1][arow] = va0.y;
        As[aq + 2][arow] = va0.z; As[aq + 3][arow] = va0.w;
        As[aq + 4][arow] = va1.x; As[aq + 5][arow] = va1.y;
        As[aq + 6][arow] = va1.z; As[aq + 7][arow] = va1.w;
        *(float4*)&B0s[bk][bn] = *(const float4*)(b0p + (size_t)kk * MDIM);
        *(float4*)&B1s[bk][bn] = *(const float4*)(b1p + (size_t)kk * MDIM);
        __syncthreads();

#pragma unroll
        for (int k = 0; k < 16; k++) {
            float a[8], b0[4], b1[4];
            *(float4*)&a[0] = *(const float4*)&As[k][ty * 8];
            *(float4*)&a[4] = *(const float4*)&As[k][ty * 8 + 4];
            *(float4*)&b0[0] = *(const float4*)&B0s[k][tx * 4];
            *(float4*)&b1[0] = *(const float4*)&B1s[k][tx * 4];
#pragma unroll
            for (int i = 0; i < 8; i++)
#pragma unroll
                for (int j = 0; j < 4; j++) {
                    c0[i][j] += a[i] * b0[j];
                    c1[i][j] += a[i] * b1[j];
                }
        }
        __syncthreads();
    }

    // epilogue: h = silu(c0) * c1
#pragma unroll
    for (int i = 0; i < 8; i++) {
        int r = ty * 8 + i;
        if (row0 + r < cnt) {
            float4 v;
            float g;
            g = c0[i][0]; v.x = (g / (1.f + __expf(-g))) * c1[i][0];
            g = c0[i][1]; v.y = (g / (1.f + __expf(-g))) * c1[i][1];
            g = c0[i][2]; v.z = (g / (1.f + __expf(-g))) * c1[i][2];
            g = c0[i][3]; v.w = (g / (1.f + __expf(-g))) * c1[i][3];
            *(float4*)(g_h + (size_t)(base + row0 + r) * MDIM + n0 + tx * 4) = v;
        }
    }
}

// ---------------- GEMM2: out += wgt * (H @ wo), scatter via atomicAdd ----------------
__global__ __launch_bounds__(256, 2) void gemm2_kernel(
        const float* __restrict__ wo, float* __restrict__ out) {
    const int e    = blockIdx.z;
    const int base = g_offsets[e];
    const int cnt  = g_offsets[e + 1] - base;
    const int row0 = blockIdx.y * 128;
    if (row0 >= cnt) return;
    const int n0 = blockIdx.x * 64;

    __shared__ float As[16][128];
    __shared__ float Bs[16][64];
    __shared__ int   stok[128];
    __shared__ float sw[128];

    const int tid = threadIdx.x;
    if (tid < 128) {
        int r = row0 + tid;
        stok[tid] = (r < cnt) ? g_tok[base + r] : -1;
        sw[tid]   = (r < cnt) ? g_wgt[base + r] : 0.f;
    }
    __syncthreads();

    const int arow = tid >> 1;
    const int aq   = (tid & 1) << 3;
    const bool avalid = (row0 + arow) < cnt;
    const float* aptr = g_h + (size_t)(base + row0 + arow) * MDIM + aq;

    const int bk = tid >> 4;
    const int bn = (tid & 15) << 2;
    const float* bp = wo + ((size_t)e * MDIM + bk) * DDIM + n0 + bn;

    const int ty = tid >> 4;
    const int tx = tid & 15;

    float c[8][4];
#pragma unroll
    for (int i = 0; i < 8; i++)
#pragma unroll
        for (int j = 0; j < 4; j++) c[i][j] = 0.f;

    for (int kk = 0; kk < MDIM; kk += 16) {
        float4 va0 = make_float4(0.f, 0.f, 0.f, 0.f), va1 = va0;
        if (avalid) {
            va0 = *(const float4*)(aptr + kk);
            va1 = *(const float4*)(aptr + kk + 4);
        }
        As[aq + 0][arow] = va0.x; As[aq + 1][arow] = va0.y;
        As[aq + 2][arow] = va0.z; As[aq + 3][arow] = va0.w;
        As[aq + 4][arow] = va1.x; As[aq + 5][arow] = va1.y;
        As[aq + 6][arow] = va1.z; As[aq + 7][arow] = va1.w;
        *(float4*)&Bs[bk][bn] = *(const float4*)(bp + (size_t)kk * DDIM);
        __syncthreads();

#pragma unroll
        for (int k = 0; k < 16; k++) {
            float a[8], b[4];
            *(float4*)&a[0] = *(const float4*)&As[k][ty * 8];
            *(float4*)&a[4] = *(const float4*)&As[k][ty * 8 + 4];
            *(float4*)&b[0] = *(const float4*)&Bs[k][tx * 4];
#pragma unroll
            for (int i = 0; i < 8; i++)
#pragma unroll
                for (int j = 0; j < 4; j++) c[i][j] += a[i] * b[j];
        }
        __syncthreads();
    }

#pragma unroll
    for (int i = 0; i < 8; i++) {
        int r = ty * 8 + i;
        if (row0 + r < cnt) {
            int   t = stok[r];
            float w = sw[r];
            float* op = out + (size_t)t * DDIM + n0 + tx * 4;
            atomicAdd(op + 0, w * c[i][0]);
            atomicAdd(op + 1, w * c[i][1]);
            atomicAdd(op + 2, w * c[i][2]);
            atomicAdd(op + 3, w * c[i][3]);
        }
    }
}

// ---------------- launch ----------------
extern "C" void kernel_launch(void* const* d_in, const int* in_sizes, int n_in,
                              void* d_out, int out_size) {
    const float* x  = (const float*)d_in[0];
    const float* wg = (const float*)d_in[1];
    const float* w0 = (const float*)d_in[2];
    const float* w1 = (const float*)d_in[3];
    const float* wo = (const float*)d_in[4];
    float* out = (float*)d_out;

    (void)in_sizes; (void)n_in; (void)out_size;

    // out is 16,777,216 floats -> 4 per thread, 256 threads/block
    zero_out_kernel<<<NTOK * DDIM / (256 * 4), 256>>>(out);
    zero_counts_kernel<<<1, 32>>>();
    route_kernel<<<NTOK / 8, 256>>>(x, wg);
    offsets_kernel<<<1, 32>>>();
    compact_kernel<<<dim3(NTOK / 256, NE), 256>>>();
    // gemm1: N-tiles = 1024/64 = 16, worst-case M-tiles = 32768/128 = 256, E = 16
    gemm1_kernel<<<dim3(16, 256, NE), 256>>>(x, w0, w1);
    // gemm2: N-tiles = 512/64 = 8
    gemm2_kernel<<<dim3(8, 256, NE), 256>>>(wo, out);
}